// round 1
// baseline (speedup 1.0000x reference)
#include <cuda_runtime.h>
#include <cuda_bf16.h>
#include <mma.h>

using namespace nvcuda;

// Problem constants (fixed shapes per reference)
#define BSZ   8192
#define DIN   4096
#define DOUT  4096

// bf16 scratch for converted operands (allowed: __device__ globals)
__device__ __align__(16) __nv_bfloat16 g_Xb[(size_t)BSZ * DIN];   // 64 MB
__device__ __align__(16) __nv_bfloat16 g_Wb[(size_t)DIN * DOUT];  // 32 MB

// ---------------------------------------------------------------------------
// Convert fp32 -> bf16 (vectorized float4 -> 8 bytes)
// ---------------------------------------------------------------------------
__global__ void convert_f32_to_bf16(const float* __restrict__ src,
                                    __nv_bfloat16* __restrict__ dst,
                                    size_t n4) {
    size_t i = (size_t)blockIdx.x * blockDim.x + threadIdx.x;
    size_t stride = (size_t)gridDim.x * blockDim.x;
    for (; i < n4; i += stride) {
        float4 v = reinterpret_cast<const float4*>(src)[i];
        __nv_bfloat162 lo = __floats2bfloat162_rn(v.x, v.y);
        __nv_bfloat162 hi = __floats2bfloat162_rn(v.z, v.w);
        uint2 packed;
        packed.x = *reinterpret_cast<unsigned int*>(&lo);
        packed.y = *reinterpret_cast<unsigned int*>(&hi);
        reinterpret_cast<uint2*>(dst)[i] = packed;
    }
}

// ---------------------------------------------------------------------------
// Tiled bf16 WMMA GEMM: C[BSZ, DOUT] = Xb @ Wb  (no bias here)
// Block tile 128x128, K-tile 32. 256 threads = 8 warps (2 x 4).
// Each warp computes 64x32 = 4x2 wmma 16x16x16 tiles.
// ---------------------------------------------------------------------------
#define BM 128
#define BN 128
#define BK 32
#define A_LD (BK + 8)   // 40 bf16 = 80B row stride (16B aligned)
#define B_LD (BN + 8)   // 136 bf16 = 272B row stride (16B aligned)

__global__ __launch_bounds__(256) void gemm_bf16_wmma(float* __restrict__ C) {
    __shared__ __align__(16) __nv_bfloat16 As[BM][A_LD];
    __shared__ __align__(16) __nv_bfloat16 Bs[BK][B_LD];

    const int bm = blockIdx.y * BM;
    const int bn = blockIdx.x * BN;
    const int tid = threadIdx.x;
    const int warp = tid >> 5;
    const int wm = (warp >> 2) * 64;   // warp row offset within block tile
    const int wn = (warp & 3) * 32;    // warp col offset within block tile

    wmma::fragment<wmma::accumulator, 16, 16, 16, float> acc[4][2];
#pragma unroll
    for (int m = 0; m < 4; m++)
#pragma unroll
        for (int n = 0; n < 2; n++)
            wmma::fill_fragment(acc[m][n], 0.0f);

    for (int k0 = 0; k0 < DIN; k0 += BK) {
        // Load A tile: 128 rows x 32 cols bf16. 512 chunks of 8 bf16 (16B).
#pragma unroll
        for (int i = 0; i < 2; i++) {
            int chunk = tid + i * 256;
            int r = chunk >> 2;            // /4 chunks per row
            int c = (chunk & 3) * 8;
            uint4 v = *reinterpret_cast<const uint4*>(
                &g_Xb[(size_t)(bm + r) * DIN + k0 + c]);
            *reinterpret_cast<uint4*>(&As[r][c]) = v;
        }
        // Load B tile: 32 rows x 128 cols bf16. 512 chunks of 8 bf16.
#pragma unroll
        for (int i = 0; i < 2; i++) {
            int chunk = tid + i * 256;
            int r = chunk >> 4;            // /16 chunks per row
            int c = (chunk & 15) * 8;
            uint4 v = *reinterpret_cast<const uint4*>(
                &g_Wb[(size_t)(k0 + r) * DOUT + bn + c]);
            *reinterpret_cast<uint4*>(&Bs[r][c]) = v;
        }
        __syncthreads();

#pragma unroll
        for (int kk = 0; kk < BK; kk += 16) {
            wmma::fragment<wmma::matrix_a, 16, 16, 16, __nv_bfloat16, wmma::row_major> af[4];
            wmma::fragment<wmma::matrix_b, 16, 16, 16, __nv_bfloat16, wmma::row_major> bf[2];
#pragma unroll
            for (int m = 0; m < 4; m++)
                wmma::load_matrix_sync(af[m], &As[wm + m * 16][kk], A_LD);
#pragma unroll
            for (int n = 0; n < 2; n++)
                wmma::load_matrix_sync(bf[n], &Bs[kk][wn + n * 16], B_LD);
#pragma unroll
            for (int m = 0; m < 4; m++)
#pragma unroll
                for (int n = 0; n < 2; n++)
                    wmma::mma_sync(acc[m][n], af[m], bf[n], acc[m][n]);
        }
        __syncthreads();
    }

    // Store raw xW to C (z half of d_out); bias + sign done in epilogue pass.
#pragma unroll
    for (int m = 0; m < 4; m++)
#pragma unroll
        for (int n = 0; n < 2; n++)
            wmma::store_matrix_sync(
                &C[(size_t)(bm + wm + m * 16) * DOUT + (bn + wn + n * 16)],
                acc[m][n], DOUT, wmma::mem_row_major);
}

// ---------------------------------------------------------------------------
// Epilogue: z = xW + b; out[0..split) = sign(z), out[split..) = z  (in-place)
// ---------------------------------------------------------------------------
__global__ void bias_sign_epilogue(const float* __restrict__ b,
                                   float* __restrict__ out, size_t split4) {
    size_t i = (size_t)blockIdx.x * blockDim.x + threadIdx.x;
    size_t stride = (size_t)gridDim.x * blockDim.x;
    float4* zp = reinterpret_cast<float4*>(out + 4 * split4);  // z half (holds xW)
    float4* sp = reinterpret_cast<float4*>(out);               // sign half
    const float4* bp = reinterpret_cast<const float4*>(b);
    for (; i < split4; i += stride) {
        float4 z = zp[i];
        float4 bb = bp[i & (DOUT / 4 - 1)];
        z.x += bb.x; z.y += bb.y; z.z += bb.z; z.w += bb.w;
        float4 s;
        s.x = (z.x >= 0.0f) ? 1.0f : -1.0f;
        s.y = (z.y >= 0.0f) ? 1.0f : -1.0f;
        s.z = (z.z >= 0.0f) ? 1.0f : -1.0f;
        s.w = (z.w >= 0.0f) ? 1.0f : -1.0f;
        zp[i] = z;
        sp[i] = s;
    }
}

// ---------------------------------------------------------------------------
extern "C" void kernel_launch(void* const* d_in, const int* in_sizes, int n_in,
                              void* d_out, int out_size) {
    const float* x = (const float*)d_in[0];   // [BSZ, DIN]
    const float* W = (const float*)d_in[1];   // [DIN, DOUT]
    const float* b = (const float*)d_in[2];   // [DOUT]
    float* out = (float*)d_out;               // [2 * BSZ * DOUT]

    const size_t split = (size_t)out_size / 2;   // BSZ*DOUT

    // Resolve device-global scratch addresses (host side, no allocation)
    __nv_bfloat16* xb_ptr = nullptr;
    __nv_bfloat16* wb_ptr = nullptr;
    cudaGetSymbolAddress((void**)&xb_ptr, g_Xb);
    cudaGetSymbolAddress((void**)&wb_ptr, g_Wb);

    // 1) Convert operands to bf16
    {
        size_t n4 = (size_t)BSZ * DIN / 4;
        int blocks = (int)((n4 + 255) / 256);
        convert_f32_to_bf16<<<blocks, 256>>>(x, xb_ptr, n4);
    }
    {
        size_t n4 = (size_t)DIN * DOUT / 4;
        int blocks = (int)((n4 + 255) / 256);
        convert_f32_to_bf16<<<blocks, 256>>>(W, wb_ptr, n4);
    }

    // 2) GEMM: write xW into z half of d_out
    {
        dim3 grid(DOUT / BN, BSZ / BM);   // (32, 64)
        gemm_bf16_wmma<<<grid, 256>>>(out + split);
    }

    // 3) Bias + sign epilogue
    {
        size_t split4 = split / 4;
        int blocks = 2048;
        bias_sign_epilogue<<<blocks, 256>>>(b, out, split4);
    }
}

// round 4
// speedup vs baseline: 1.8684x; 1.8684x over previous
#include <cuda_runtime.h>
#include <cuda_bf16.h>
#include <cstdint>

// ===========================================================================
// out = (sign(x@W + b), x@W + b); x[8192,4096] f32, W[4096,4096] ternary, b=512
// sm_103 build target has NO tcgen05 (needs sm_103a feature). Use legacy
// mma.sync m16n8k16 bf16 with cp.async 3-stage pipeline + fused epilogue.
// ===========================================================================
#define BSZ   8192
#define DIN   4096
#define DOUT  4096

__device__ __align__(1024) __nv_bfloat16 g_Xb[(size_t)BSZ * DIN];   // 64 MB [m][k]
__device__ __align__(1024) __nv_bfloat16 g_Wt[(size_t)DOUT * DIN];  // 32 MB [n][k]

__device__ __forceinline__ uint32_t smem_u32(const void* p) {
    uint32_t a;
    asm("{ .reg .u64 t; cvta.to.shared.u64 t, %1; cvt.u32.u64 %0, t; }"
        : "=r"(a) : "l"(p));
    return a;
}

#define SW128(o) ((o) ^ (((o) >> 3) & 0x70))
#define CP16(dst, src) \
    asm volatile("cp.async.cg.shared.global [%0], [%1], 16;" :: "r"(dst), "l"(src))
#define CP_COMMIT() asm volatile("cp.async.commit_group;" ::: "memory")
#define CP_WAIT(N)  asm volatile("cp.async.wait_group %0;" :: "n"(N) : "memory")

#define LDSM_X4(r0, r1, r2, r3, addr) \
    asm volatile("ldmatrix.sync.aligned.m8n8.x4.shared.b16 {%0,%1,%2,%3}, [%4];" \
                 : "=r"(r0), "=r"(r1), "=r"(r2), "=r"(r3) : "r"(addr))

#define MMA16816(d, a0, a1, a2, a3, b0, b1) \
    asm volatile("mma.sync.aligned.m16n8k16.row.col.f32.bf16.bf16.f32 " \
                 "{%0,%1,%2,%3},{%4,%5,%6,%7},{%8,%9},{%0,%1,%2,%3};" \
                 : "+f"((d)[0]), "+f"((d)[1]), "+f"((d)[2]), "+f"((d)[3]) \
                 : "r"(a0), "r"(a1), "r"(a2), "r"(a3), "r"(b0), "r"(b1))

// ---------------------------------------------------------------------------
// GEMM config: BM=128, BN=256, BK=64, 3 stages, 256 threads (8 warps 2x4),
// warp tile 64x64.
// ---------------------------------------------------------------------------
#define BM 128
#define BN 256
#define BK 64
#define STAGES 3
#define NT (DIN / BK)                       // 64 K-tiles
#define A_BYTES (BM * BK * 2)               // 16384
#define B_BYTES (BN * BK * 2)               // 32768
#define STAGE_BYTES (A_BYTES + B_BYTES)     // 49152
#define SMEM_TOTAL (STAGES * STAGE_BYTES)   // 147456

__global__ __launch_bounds__(256, 1) void gemm_hmma(
    const float* __restrict__ bias,
    float* __restrict__ out_sign,
    float* __restrict__ out_z) {
    extern __shared__ char smem[];
    const uint32_t sbase = smem_u32(smem);
    const int tid = threadIdx.x;
    const int lane = tid & 31;
    const int wid = tid >> 5;
    const int bm = blockIdx.y * BM;
    const int bn = blockIdx.x * BN;
    const int wm = (wid >> 2) * 64;   // warp row offset in CTA tile
    const int wn = (wid & 3) * 64;    // warp col offset in CTA tile

    const __nv_bfloat16* Ag = g_Xb + (size_t)bm * DIN;
    const __nv_bfloat16* Bg = g_Wt + (size_t)bn * DIN;

    // --- stage loader: A 1024 chunks (4/thread), B 2048 chunks (8/thread) ---
    auto load_stage = [&](int st, int kt) {
        const uint32_t sa = sbase + st * STAGE_BYTES;
        const uint32_t sb = sa + A_BYTES;
        const __nv_bfloat16* a = Ag + kt * BK;
        const __nv_bfloat16* b = Bg + kt * BK;
#pragma unroll
        for (int i = 0; i < 4; i++) {
            int ch = tid + i * 256;
            int r = ch >> 3, c = ch & 7;
            CP16(sa + SW128((uint32_t)(r * 128 + c * 16)),
                 (const void*)(a + (size_t)r * DIN + c * 8));
        }
#pragma unroll
        for (int i = 0; i < 8; i++) {
            int ch = tid + i * 256;
            int r = ch >> 3, c = ch & 7;
            CP16(sb + SW128((uint32_t)(r * 128 + c * 16)),
                 (const void*)(b + (size_t)r * DIN + c * 8));
        }
    };

    load_stage(0, 0); CP_COMMIT();
    load_stage(1, 1); CP_COMMIT();

    float acc[4][8][4];
#pragma unroll
    for (int mt = 0; mt < 4; mt++)
#pragma unroll
        for (int nt = 0; nt < 8; nt++)
#pragma unroll
            for (int q = 0; q < 4; q++) acc[mt][nt][q] = 0.0f;

    // Per-thread ldmatrix address components (byte offsets, pre-swizzle)
    const int a_row = (lane & 15);            // + wm + mt*16
    const int a_csel = (lane >> 4) * 16;      // + kk*32
    const int b_row = ((lane >> 4) & 1) * 8 + (lane & 7);  // + wn + np*16
    const int b_csel = ((lane >> 3) & 1) * 16;

    for (int s = 0; s < NT; s++) {
        CP_WAIT(1);
        __syncthreads();
        if (s + 2 < NT) load_stage((s + 2) % STAGES, s + 2);
        CP_COMMIT();

        const uint32_t sa = sbase + (s % STAGES) * STAGE_BYTES;
        const uint32_t sb = sa + A_BYTES;
#pragma unroll
        for (int kk = 0; kk < 4; kk++) {
            uint32_t ar[4][4], br[4][4];
#pragma unroll
            for (int mt = 0; mt < 4; mt++) {
                uint32_t off = (uint32_t)((wm + mt * 16 + a_row) * 128 +
                                          kk * 32 + a_csel);
                LDSM_X4(ar[mt][0], ar[mt][1], ar[mt][2], ar[mt][3],
                        sa + SW128(off));
            }
#pragma unroll
            for (int np = 0; np < 4; np++) {
                uint32_t off = (uint32_t)((wn + np * 16 + b_row) * 128 +
                                          kk * 32 + b_csel);
                LDSM_X4(br[np][0], br[np][1], br[np][2], br[np][3],
                        sb + SW128(off));
            }
#pragma unroll
            for (int mt = 0; mt < 4; mt++)
#pragma unroll
                for (int nt = 0; nt < 8; nt++)
                    MMA16816(acc[mt][nt],
                             ar[mt][0], ar[mt][1], ar[mt][2], ar[mt][3],
                             br[nt >> 1][(nt & 1) * 2],
                             br[nt >> 1][(nt & 1) * 2 + 1]);
        }
    }

    // --- fused epilogue: bias + sign, straight from accumulators ---
#pragma unroll
    for (int mt = 0; mt < 4; mt++) {
        const int r0 = bm + wm + mt * 16 + (lane >> 2);
        const size_t base0 = (size_t)r0 * DOUT;
        const size_t base1 = base0 + 8 * DOUT;
#pragma unroll
        for (int nt = 0; nt < 8; nt++) {
            const int c = bn + wn + nt * 8 + (lane & 3) * 2;
            const float2 bb = *reinterpret_cast<const float2*>(bias + c);
            float2 z0, z1, s0, s1;
            z0.x = acc[mt][nt][0] + bb.x;
            z0.y = acc[mt][nt][1] + bb.y;
            z1.x = acc[mt][nt][2] + bb.x;
            z1.y = acc[mt][nt][3] + bb.y;
            s0.x = (z0.x >= 0.0f) ? 1.0f : -1.0f;
            s0.y = (z0.y >= 0.0f) ? 1.0f : -1.0f;
            s1.x = (z1.x >= 0.0f) ? 1.0f : -1.0f;
            s1.y = (z1.y >= 0.0f) ? 1.0f : -1.0f;
            *reinterpret_cast<float2*>(out_z + base0 + c) = z0;
            *reinterpret_cast<float2*>(out_sign + base0 + c) = s0;
            *reinterpret_cast<float2*>(out_z + base1 + c) = z1;
            *reinterpret_cast<float2*>(out_sign + base1 + c) = s1;
        }
    }
}

// ---------------------------------------------------------------------------
// x fp32 -> bf16
// ---------------------------------------------------------------------------
__global__ void convert_f32_to_bf16(const float* __restrict__ src,
                                    __nv_bfloat16* __restrict__ dst,
                                    size_t n4) {
    size_t i = (size_t)blockIdx.x * blockDim.x + threadIdx.x;
    size_t stride = (size_t)gridDim.x * blockDim.x;
    for (; i < n4; i += stride) {
        float4 v = reinterpret_cast<const float4*>(src)[i];
        __nv_bfloat162 lo = __floats2bfloat162_rn(v.x, v.y);
        __nv_bfloat162 hi = __floats2bfloat162_rn(v.z, v.w);
        uint2 packed;
        packed.x = *reinterpret_cast<unsigned int*>(&lo);
        packed.y = *reinterpret_cast<unsigned int*>(&hi);
        reinterpret_cast<uint2*>(dst)[i] = packed;
    }
}

// ---------------------------------------------------------------------------
// W[k][n] f32 -> Wt[n][k] bf16 (32x32 smem transpose)
// ---------------------------------------------------------------------------
__global__ __launch_bounds__(256) void transpose_w_bf16(
    const float* __restrict__ W, __nv_bfloat16* __restrict__ Wt) {
    __shared__ __nv_bfloat16 t[32][33];
    const int n0 = blockIdx.x * 32;
    const int k0 = blockIdx.y * 32;
    const int tx = threadIdx.x & 31;
    const int ty = threadIdx.x >> 5;
#pragma unroll
    for (int i = 0; i < 4; i++)
        t[ty + i * 8][tx] =
            __float2bfloat16(W[(size_t)(k0 + ty + i * 8) * DOUT + n0 + tx]);
    __syncthreads();
#pragma unroll
    for (int i = 0; i < 4; i++)
        Wt[(size_t)(n0 + ty + i * 8) * DIN + k0 + tx] = t[tx][ty + i * 8];
}

// ---------------------------------------------------------------------------
extern "C" void kernel_launch(void* const* d_in, const int* in_sizes, int n_in,
                              void* d_out, int out_size) {
    const float* x = (const float*)d_in[0];
    const float* W = (const float*)d_in[1];
    const float* b = (const float*)d_in[2];
    float* out = (float*)d_out;
    const size_t split = (size_t)out_size / 2;

    __nv_bfloat16* xb_ptr = nullptr;
    __nv_bfloat16* wt_ptr = nullptr;
    cudaGetSymbolAddress((void**)&xb_ptr, g_Xb);
    cudaGetSymbolAddress((void**)&wt_ptr, g_Wt);

    {
        size_t n4 = (size_t)BSZ * DIN / 4;
        convert_f32_to_bf16<<<(int)((n4 + 255) / 256), 256>>>(x, xb_ptr, n4);
    }
    {
        dim3 grid(DOUT / 32, DIN / 32);
        transpose_w_bf16<<<grid, 256>>>(W, wt_ptr);
    }
    {
        cudaFuncSetAttribute(gemm_hmma,
                             cudaFuncAttributeMaxDynamicSharedMemorySize,
                             SMEM_TOTAL);
        dim3 grid(DOUT / BN, BSZ / BM);   // (16, 64)
        gemm_hmma<<<grid, 256, SMEM_TOTAL>>>(b, out, out + split);
    }
}